// round 17
// baseline (speedup 1.0000x reference)
#include <cuda_runtime.h>
#include <cuda_fp16.h>
#include <cstdint>

#define D_MODEL 1024
#define N_HEADS 16
#define D_HEAD  64
#define BATCH   2
#define SEQ     2048
#define M_ROWS  (BATCH * SEQ)      // 4096

// Q pre-scale: 1/sqrt(Dh) * log2(e)  (softmax computed in exp2 domain)
#define QSCALE 0.1803368801111204f

// ---------------- scratch (no allocations allowed) ----------------
__device__ __half g_Qh[(size_t)BATCH * N_HEADS * SEQ * D_HEAD];
__device__ __half g_Ql[(size_t)BATCH * N_HEADS * SEQ * D_HEAD];
__device__ __half g_Kh[(size_t)BATCH * N_HEADS * SEQ * D_HEAD];   // single fp16 K
__device__ __half g_Vh[(size_t)BATCH * N_HEADS * SEQ * D_HEAD];   // single fp16 V

__device__ __half g_xh[(size_t)M_ROWS * D_MODEL];                 // x split fp16
__device__ __half g_xl[(size_t)M_ROWS * D_MODEL];
__device__ __half g_Ah[(size_t)M_ROWS * D_MODEL];                 // attn out split fp16
__device__ __half g_Al[(size_t)M_ROWS * D_MODEL];
__device__ __half g_Wt[(size_t)4 * D_MODEL * D_MODEL];            // W^T single fp16 [4][n][k]

// ---------------- helpers ----------------
__device__ __forceinline__ uint32_t smem_u32(const void* p) {
    uint32_t a;
    asm("{ .reg .u64 t; cvta.to.shared.u64 t, %1; cvt.u32.u64 %0, t; }" : "=r"(a) : "l"(p));
    return a;
}
__device__ __forceinline__ void cp_async16(uint32_t sa, const void* g) {
    asm volatile("cp.async.cg.shared.global [%0], [%1], 16;\n" :: "r"(sa), "l"(g));
}
__device__ __forceinline__ void ldmat4(uint32_t* r, uint32_t addr) {
    asm volatile("ldmatrix.sync.aligned.m8n8.x4.shared.b16 {%0,%1,%2,%3}, [%4];"
        : "=r"(r[0]), "=r"(r[1]), "=r"(r[2]), "=r"(r[3]) : "r"(addr));
}
__device__ __forceinline__ void ldmat4t(uint32_t* r, uint32_t addr) {
    asm volatile("ldmatrix.sync.aligned.m8n8.x4.trans.shared.b16 {%0,%1,%2,%3}, [%4];"
        : "=r"(r[0]), "=r"(r[1]), "=r"(r[2]), "=r"(r[3]) : "r"(addr));
}
__device__ __forceinline__ void mma_fp(float* c, const uint32_t* a, const uint32_t* b) {
    asm volatile("mma.sync.aligned.m16n8k16.row.col.f32.f16.f16.f32 "
        "{%0,%1,%2,%3}, {%4,%5,%6,%7}, {%8,%9}, {%0,%1,%2,%3};"
        : "+f"(c[0]), "+f"(c[1]), "+f"(c[2]), "+f"(c[3])
        : "r"(a[0]), "r"(a[1]), "r"(a[2]), "r"(a[3]), "r"(b[0]), "r"(b[1]));
}
__device__ __forceinline__ float fexp2(float x) {
    float r; asm("ex2.approx.f32 %0, %1;" : "=f"(r) : "f"(x)); return r;
}
__device__ __forceinline__ uint32_t ex2h2(uint32_t a) {
    uint32_t r; asm("ex2.approx.f16x2 %0, %1;" : "=r"(r) : "r"(a)); return r;
}
__device__ __forceinline__ uint32_t pack2(float x, float y) {
    uint32_t r; asm("cvt.rn.f16x2.f32 %0, %1, %2;" : "=r"(r) : "f"(y), "f"(x)); return r;
}
__device__ __forceinline__ float2 unpack2(uint32_t u) {
    __half2 h; *reinterpret_cast<uint32_t*>(&h) = u;
    return __half22float2(h);
}

// ---------------- conversion kernels ----------------
__global__ __launch_bounds__(256) void cvt_rm(const float* __restrict__ src)
{
    const size_t i4 = (size_t)blockIdx.x * blockDim.x + threadIdx.x;
    if (i4 < (size_t)M_ROWS * D_MODEL / 4) {
        float4 v = ((const float4*)src)[i4];
        float vv[4] = {v.x, v.y, v.z, v.w};
#pragma unroll
        for (int j = 0; j < 4; j++) {
            __half h = __float2half_rn(vv[j]);
            g_xh[i4 * 4 + j] = h;
            g_xl[i4 * 4 + j] = __float2half_rn(vv[j] - __half2float(h));
        }
    }
}

__global__ __launch_bounds__(256) void cvt_wt(const float* __restrict__ Wq,
                                              const float* __restrict__ Wk,
                                              const float* __restrict__ Wv,
                                              const float* __restrict__ Wo)
{
    __shared__ float t[32][33];
    const int z = blockIdx.z;
    const float* W = (z == 0) ? Wq : (z == 1) ? Wk : (z == 2) ? Wv : Wo;
    __half* dst = g_Wt + (size_t)z * D_MODEL * D_MODEL;
    const int n0 = blockIdx.x * 32, k0 = blockIdx.y * 32;
    const int tx = threadIdx.x & 31, ty = threadIdx.x >> 5;
    for (int r = ty; r < 32; r += 8)
        t[r][tx] = W[(size_t)(k0 + r) * D_MODEL + n0 + tx];
    __syncthreads();
    for (int r = ty; r < 32; r += 8)
        dst[(size_t)(n0 + r) * D_MODEL + k0 + tx] = __float2half_rn(t[tx][r]);
}

// ---------------- fused QKV GEMM: 512 thr / 16 warps, warp tile 32x32 ----------------
#define AST2   72
#define TILEB2 (128 * AST2 * 2)        // 18432 B per 128x64 fp16 tile
#define KC2    64
#define NKC2   (D_MODEL / KC2)         // 16 chunks
#define QSTAGE (5 * TILEB2)            // 92160 B : [Ah, Al, BQ, BK, BV]

__device__ __forceinline__ void load_chunk_qkv(uint32_t bufbase, int c, int tid,
        const __half* const* gs)
{
#pragma unroll
    for (int i = 0; i < 10; i++) {
        const int idx = i * 512 + tid;
        const int t = idx >> 10;           // tile 0..4 (constant per i)
        const int rem = idx & 1023;
        const int row = rem >> 3;
        const int seg = rem & 7;
        cp_async16(bufbase + t * TILEB2 + row * (AST2 * 2) + seg * 16,
                   gs[t] + (size_t)row * D_MODEL + c * KC2 + seg * 8);
    }
    asm volatile("cp.async.commit_group;\n" ::: "memory");
}

__global__ __launch_bounds__(512, 1) void gemm_qkv(
        const float* __restrict__ bq, const float* __restrict__ bk,
        const float* __restrict__ bv)
{
    extern __shared__ char smem[];
    const uint32_t sb = smem_u32(smem);
    const int tid = threadIdx.x;
    const int wid = tid >> 5, lane = tid & 31;
    const int wy = wid & 3, wx = wid >> 2;       // warp grid 4(m) x 4(n)
    const int rowBase = blockIdx.y * 128;
    const int colBase = blockIdx.x * 128;

    const __half* gs[5];
    gs[0] = g_xh + (size_t)rowBase * D_MODEL;
    gs[1] = g_xl + (size_t)rowBase * D_MODEL;
#pragma unroll
    for (int z = 0; z < 3; z++)
        gs[2 + z] = g_Wt + (size_t)z * D_MODEL * D_MODEL + (size_t)colBase * D_MODEL;

    const uint32_t buf0 = sb, buf1 = sb + QSTAGE;

    float acc[3][2][4][4];
#pragma unroll
    for (int z = 0; z < 3; z++)
#pragma unroll
        for (int mt = 0; mt < 2; mt++)
#pragma unroll
            for (int nt = 0; nt < 4; nt++)
#pragma unroll
                for (int j = 0; j < 4; j++) acc[z][mt][nt][j] = 0.f;

    load_chunk_qkv(buf0, 0, tid, gs);
    load_chunk_qkv(buf1, 1, tid, gs);

    const int arow = (lane & 7) + ((lane >> 3) & 1) * 8;
    const int acol = (lane >> 4) * 8;
    const int brow = (lane & 7) + (lane >> 4) * 8;
    const int bcol = ((lane >> 3) & 1) * 8;

    for (int c = 0; c < NKC2; c++) {
        const int b = c & 1;
        if (c < NKC2 - 1) asm volatile("cp.async.wait_group 1;\n" ::: "memory");
        else              asm volatile("cp.async.wait_group 0;\n" ::: "memory");
        __syncthreads();

        const uint32_t base = b ? buf1 : buf0;

#pragma unroll
        for (int ks = 0; ks < 4; ks++) {
            uint32_t ah[2][4], al[2][4];
#pragma unroll
            for (int mt = 0; mt < 2; mt++) {
                const uint32_t off = (uint32_t)(wy * 32 + mt * 16 + arow) * (AST2 * 2)
                                   + (uint32_t)(ks * 16 + acol) * 2;
                ldmat4(ah[mt], base + off);
                ldmat4(al[mt], base + TILEB2 + off);
            }
#pragma unroll
            for (int z = 0; z < 3; z++) {
#pragma unroll
                for (int np = 0; np < 2; np++) {
                    uint32_t bw[4];
                    const uint32_t off = (uint32_t)(wx * 32 + np * 16 + brow) * (AST2 * 2)
                                       + (uint32_t)(ks * 16 + bcol) * 2;
                    ldmat4(bw, base + (2 + z) * TILEB2 + off);
#pragma unroll
                    for (int mt = 0; mt < 2; mt++) {
                        mma_fp(acc[z][mt][np * 2],     ah[mt], &bw[0]);
                        mma_fp(acc[z][mt][np * 2 + 1], ah[mt], &bw[2]);
                        mma_fp(acc[z][mt][np * 2],     al[mt], &bw[0]);
                        mma_fp(acc[z][mt][np * 2 + 1], al[mt], &bw[2]);
                    }
                }
            }
        }
        __syncthreads();
        if (c + 2 < NKC2)
            load_chunk_qkv(b ? buf1 : buf0, c + 2, tid, gs);
    }

    // epilogue: Q split-fp16, K/V single fp16
#pragma unroll
    for (int z = 0; z < 3; z++) {
        const float* bias = (z == 0) ? bq : (z == 1) ? bk : bv;
        __half* dH = (z == 0) ? g_Qh : (z == 1) ? g_Kh : g_Vh;
        const float sc = (z == 0) ? QSCALE : 1.0f;
#pragma unroll
        for (int mt = 0; mt < 2; mt++) {
#pragma unroll
            for (int nt = 0; nt < 4; nt++) {
                const int col0 = colBase + wx * 32 + nt * 8 + (lane & 3) * 2;
                const int hh = col0 >> 6, d0 = col0 & (D_HEAD - 1);
                const float b0 = bias[col0], b1 = bias[col0 + 1];
#pragma unroll
                for (int half_m = 0; half_m < 2; half_m++) {
                    const int row = rowBase + wy * 32 + mt * 16 + (lane >> 2) + half_m * 8;
                    const int bb = row >> 11, s = row & (SEQ - 1);
                    float v0 = (acc[z][mt][nt][half_m * 2]     + b0) * sc;
                    float v1 = (acc[z][mt][nt][half_m * 2 + 1] + b1) * sc;
                    const uint32_t hpair = pack2(v0, v1);
                    const size_t e = (((size_t)(bb * N_HEADS + hh)) * SEQ + s) * D_HEAD + d0;
                    *(uint32_t*)(dH + e) = hpair;
                    if (z == 0) {
                        float2 f = unpack2(hpair);
                        *(uint32_t*)(g_Ql + e) = pack2(v0 - f.x, v1 - f.y);
                    }
                }
            }
        }
    }
}

// ---------------- Wo GEMM: A split (2-pass), W single; 2 CTAs/SM ----------------
#define AST   40
#define TILEB (128 * AST * 2)          // 10240 B per 128x32 fp16 tile
#define KC    32
#define NKC   (D_MODEL / KC)           // 32 chunks
#define WSTAGE (3 * TILEB)             // Ah, Al, B = 30720 B

__device__ __forceinline__ void load_chunk_wo(uint32_t bufbase, int c, int tid,
        const __half* g0, const __half* g1, const __half* g2)
{
    const __half* gs[3] = {g0, g1, g2};
#pragma unroll
    for (int i = 0; i < 6; i++) {
        const int idx = i * 256 + tid;
        const int t = idx >> 9;
        const int rem = idx & 511;
        const int row = rem >> 2;
        const int seg = rem & 3;
        cp_async16(bufbase + t * TILEB + row * (AST * 2) + seg * 16,
                   gs[t] + (size_t)row * D_MODEL + c * KC + seg * 8);
    }
    asm volatile("cp.async.commit_group;\n" ::: "memory");
}

__global__ __launch_bounds__(256, 2) void gemm_wo(float* __restrict__ out)
{
    extern __shared__ char smem[];
    const uint32_t sb = smem_u32(smem);
    const int tid = threadIdx.x;
    const int wid = tid >> 5, lane = tid & 31;
    const int wy = wid & 3, wx = wid >> 2;
    const int rowBase = blockIdx.y * 128;
    const int colBase = blockIdx.x * 128;

    const __half* Ah = g_Ah + (size_t)rowBase * D_MODEL;
    const __half* Al = g_Al + (size_t)rowBase * D_MODEL;
    const __half* Bw = g_Wt + (size_t)3 * D_MODEL * D_MODEL + (size_t)colBase * D_MODEL;

    const uint32_t buf0 = sb, buf1 = sb + WSTAGE;

    float acc[2][8][4];
#pragma unroll
    for (int mt = 0; mt < 2; mt++)
#pragma unroll
        for (int nt = 0; nt < 8; nt++)
#pragma unroll
            for (int j = 0; j < 4; j++) acc[mt][nt][j] = 0.f;

    load_chunk_wo(buf0, 0, tid, Ah, Al, Bw);
    load_chunk_wo(buf1, 1, tid, Ah, Al, Bw);

    const int arow = (lane & 7) + ((lane >> 3) & 1) * 8;
    const int acol = (lane >> 4) * 8;
    const int brow = (lane & 7) + (lane >> 4) * 8;
    const int bcol = ((lane >> 3) & 1) * 8;

    for (int c = 0; c < NKC; c++) {
        const int b = c & 1;
        if (c < NKC - 1) asm volatile("cp.async.wait_group 1;\n" ::: "memory");
        else             asm volatile("cp.async.wait_group 0;\n" ::: "memory");
        __syncthreads();

        const uint32_t base = b ? buf1 : buf0;
        const uint32_t aHs = base, aLs = base + TILEB, bWs = base + 2 * TILEB;

#pragma unroll
        for (int ks = 0; ks < 2; ks++) {
            uint32_t ah[2][4], al[2][4];
#pragma unroll
            for (int mt = 0; mt < 2; mt++) {
                const uint32_t off = (uint32_t)(wy * 32 + mt * 16 + arow) * (AST * 2)
                                   + (uint32_t)(ks * 16 + acol) * 2;
                ldmat4(ah[mt], aHs + off);
                ldmat4(al[mt], aLs + off);
            }
#pragma unroll
            for (int np = 0; np < 4; np++) {
                uint32_t bw[4];
                const uint32_t off = (uint32_t)(wx * 64 + np * 16 + brow) * (AST * 2)
                                   + (uint32_t)(ks * 16 + bcol) * 2;
                ldmat4(bw, bWs + off);
#pragma unroll
                for (int mt = 0; mt < 2; mt++) {
                    mma_fp(acc[mt][np * 2],     ah[mt], &bw[0]);
                    mma_fp(acc[mt][np * 2 + 1], ah[mt], &bw[2]);
                    mma_fp(acc[mt][np * 2],     al[mt], &bw[0]);
                    mma_fp(acc[mt][np * 2 + 1], al[mt], &bw[2]);
                }
            }
        }
        __syncthreads();
        if (c + 2 < NKC)
            load_chunk_wo(b ? buf1 : buf0, c + 2, tid, Ah, Al, Bw);
    }

#pragma unroll
    for (int mt = 0; mt < 2; mt++)
#pragma unroll
        for (int nt = 0; nt < 8; nt++)
#pragma unroll
            for (int j = 0; j < 4; j++) {
                const int row = rowBase + wy * 32 + mt * 16 + (lane >> 2) + (j >> 1) * 8;
                const int col = colBase + wx * 64 + nt * 8 + (lane & 3) * 2 + (j & 1);
                out[(size_t)row * D_MODEL + col] = acc[mt][nt][j];
            }
}

// ---------------- tensor-core flash attention ----------------
// BK=128, LPT; softmax via ex2.f16x2; P single fp16; l via ones-MMA
#define FBK    128
#define FST    72
#define QTILE  (128 * FST)             // halves
#define KTILE  (128 * FST)             // halves
#define KVSTG  (2 * KTILE)             // Kh, Vh

__device__ __forceinline__ void load_kv(__half* stagep, int kb, int tid,
        const __half* gK, const __half* gV)
{
#pragma unroll
    for (int i = 0; i < 8; i++) {
        const int idx = i * 256 + tid;
        const int t = idx >> 10;
        const int rem = idx & 1023;
        const int row = rem >> 3;
        const int seg = rem & 7;
        const __half* g = (t == 0 ? gK : gV) + (size_t)(kb + row) * D_HEAD + seg * 8;
        cp_async16(smem_u32(stagep + t * KTILE + row * FST + seg * 8), g);
    }
    asm volatile("cp.async.commit_group;\n" ::: "memory");
}

__global__ __launch_bounds__(256, 1) void flash_mma()
{
    extern __shared__ __half fsm[];
    const int tid = threadIdx.x;
    const int wid = tid >> 5, lane = tid & 31;
    const int qt = gridDim.x - 1 - blockIdx.x;   // LPT: heavy tiles first
    const int h = blockIdx.y, b = blockIdx.z;
    const int bh = b * N_HEADS + h;
    const int qBase = qt * 128;
    const size_t gbase = (size_t)bh * SEQ * D_HEAD;

    const __half* gQh = g_Qh + gbase;
    const __half* gQl = g_Ql + gbase;
    const __half* gK  = g_Kh + gbase;
    const __half* gV  = g_Vh + gbase;

    __half* sQh = fsm;
    __half* sQl = fsm + QTILE;
    __half* stage0 = fsm + 2 * QTILE;
    __half* stage1 = stage0 + KVSTG;

    // Q tile load (group 0)
#pragma unroll
    for (int i = 0; i < 8; i++) {
        const int idx = i * 256 + tid;
        const int t = idx >> 10;
        const int rem = idx & 1023;
        const int row = rem >> 3;
        const int seg = rem & 7;
        const __half* g = (t ? gQl : gQh) + (size_t)(qBase + row) * D_HEAD + seg * 8;
        cp_async16(smem_u32((t ? sQl : sQh) + row * FST + seg * 8), g);
    }
    asm volatile("cp.async.commit_group;\n" ::: "memory");

    const int nkt = qt + 1;
    load_kv(stage0, 0, tid, gK, gV);
    load_kv(stage1, FBK, tid, gK, gV);

    const int arow = (lane & 7) + ((lane >> 3) & 1) * 8;
    const int acol = (lane >> 4) * 8;
    const int brow = (lane & 7) + (lane >> 4) * 8;
    const int bcol = ((lane >> 3) & 1) * 8;
    const int trow = (lane & 7) + ((lane >> 3) & 1) * 8;
    const int tcol = (lane >> 4) * 8;

    uint32_t qh[4][4], ql[4][4];
    float o[8][4];
#pragma unroll
    for (int nb = 0; nb < 8; nb++)
#pragma unroll
        for (int j = 0; j < 4; j++) o[nb][j] = 0.f;
    float m0 = -1e30f, m1 = -1e30f, l0 = 0.f, l1 = 0.f;

    const int row0 = qBase + wid * 16 + (lane >> 2);
    const int row1 = row0 + 8;

    const uint32_t ones2 = 0x3C003C00u;          // half2(1.0, 1.0)
    uint32_t bones[2] = {ones2, ones2};

    for (int jt = 0; jt < nkt; jt++) {
        __half* stg = (jt & 1) ? stage1 : stage0;
        if (jt < nkt - 1) asm volatile("cp.async.wait_group 1;\n" ::: "memory");
        else              asm volatile("cp.async.wait_group 0;\n" ::: "memory");
        __syncthreads();

        if (jt == 0) {
#pragma unroll
            for (int kk = 0; kk < 4; kk++) {
                const uint32_t off = (uint32_t)(wid * 16 + arow) * (FST * 2)
                                   + (uint32_t)(kk * 16 + acol) * 2;
                ldmat4(qh[kk], smem_u32(sQh) + off);
                ldmat4(ql[kk], smem_u32(sQl) + off);
            }
        }

        const uint32_t sK = smem_u32(stg);
        const uint32_t sV = sK + KTILE * 2;

        float s[16][4];
#pragma unroll
        for (int nb = 0; nb < 16; nb++)
#pragma unroll
            for (int j = 0; j < 4; j++) s[nb][j] = 0.f;

        // ---- S = Q K^T : 2 passes (qh*k + ql*k) ----
#pragma unroll
        for (int kk = 0; kk < 4; kk++) {
#pragma unroll
            for (int np = 0; np < 8; np++) {
                uint32_t bk4[4];
                const uint32_t off = (uint32_t)(np * 16 + brow) * (FST * 2)
                                   + (uint32_t)(kk * 16 + bcol) * 2;
                ldmat4(bk4, sK + off);
                mma_fp(s[np * 2],     qh[kk], &bk4[0]);
                mma_fp(s[np * 2 + 1], qh[kk], &bk4[2]);
                mma_fp(s[np * 2],     ql[kk], &bk4[0]);
                mma_fp(s[np * 2 + 1], ql[kk], &bk4[2]);
            }
        }

        // ---- causal mask (diagonal tile only) ----
        if (jt == qt) {
            const int kb = jt * FBK;
#pragma unroll
            for (int nb = 0; nb < 16; nb++) {
#pragma unroll
                for (int j = 0; j < 4; j++) {
                    const int key = kb + nb * 8 + (lane & 3) * 2 + (j & 1);
                    const int qr = (j < 2) ? row0 : row1;
                    if (key > qr) s[nb][j] = -1e30f;
                }
            }
        }

        // ---- online softmax: max in fp32, exp in fp16x2 ----
        float mx0 = -1e30f, mx1 = -1e30f;
#pragma unroll
        for (int nb = 0; nb < 16; nb++) {
            mx0 = fmaxf(mx0, fmaxf(s[nb][0], s[nb][1]));
            mx1 = fmaxf(mx1, fmaxf(s[nb][2], s[nb][3]));
        }
        mx0 = fmaxf(mx0, __shfl_xor_sync(0xffffffffu, mx0, 1));
        mx0 = fmaxf(mx0, __shfl_xor_sync(0xffffffffu, mx0, 2));
        mx1 = fmaxf(mx1, __shfl_xor_sync(0xffffffffu, mx1, 1));
        mx1 = fmaxf(mx1, __shfl_xor_sync(0xffffffffu, mx1, 2));
        const float mn0 = fmaxf(m0, mx0), mn1 = fmaxf(m1, mx1);
        const float c0 = fexp2(m0 - mn0), c1 = fexp2(m1 - mn1);
        m0 = mn0; m1 = mn1;

        // p[nb][0] = half2 probs for row0 cols (j0,j1); p[nb][1] for row1 (j2,j3)
        uint32_t p[16][2];
#pragma unroll
        for (int nb = 0; nb < 16; nb++) {
            p[nb][0] = ex2h2(pack2(s[nb][0] - m0, s[nb][1] - m0));
            p[nb][1] = ex2h2(pack2(s[nb][2] - m1, s[nb][3] - m1));
        }

        // rescale O accumulator
#pragma unroll
        for (int nb = 0; nb < 8; nb++) {
            o[nb][0] *= c0; o[nb][1] *= c0;
            o[nb][2] *= c1; o[nb][3] *= c1;
        }

        // ---- O += P V  and  row sums via ones-MMA (exact fp32) ----
        float lsum[4] = {0.f, 0.f, 0.f, 0.f};
#pragma unroll
        for (int kk = 0; kk < 8; kk++) {
            uint32_t aH[4];
            aH[0] = p[2 * kk][0];
            aH[1] = p[2 * kk][1];
            aH[2] = p[2 * kk + 1][0];
            aH[3] = p[2 * kk + 1][1];
            mma_fp(lsum, aH, bones);           // lsum[0]=row0 sum, lsum[2]=row1 sum
#pragma unroll
            for (int np = 0; np < 4; np++) {
                uint32_t bv[4];
                const uint32_t off = (uint32_t)(kk * 16 + trow) * (FST * 2)
                                   + (uint32_t)(np * 16 + tcol) * 2;
                ldmat4t(bv, sV + off);
                mma_fp(o[np * 2],     aH, &bv[0]);
                mma_fp(o[np * 2 + 1], aH, &bv[2]);
            }
        }
        l0 = l0 * c0 + lsum[0];
        l1 = l1 * c1 + lsum[2];

        __syncthreads();
        if (jt + 2 < nkt)
            load_kv(stg, (jt + 2) * FBK, tid, gK, gV);
    }

    // ---- epilogue: normalize, split-fp16, write g_Ah/g_Al ----
    const float inv0 = 1.f / l0, inv1 = 1.f / l1;
#pragma unroll
    for (int nb = 0; nb < 8; nb++) {
        const int d0 = h * D_HEAD + nb * 8 + (lane & 3) * 2;
#pragma unroll
        for (int half_m = 0; half_m < 2; half_m++) {
            const int row = half_m ? row1 : row0;
            const float inv = half_m ? inv1 : inv0;
            const float v0 = o[nb][half_m * 2] * inv;
            const float v1 = o[nb][half_m * 2 + 1] * inv;
            const uint32_t uh = pack2(v0, v1);
            float2 f = unpack2(uh);
            const uint32_t ul = pack2(v0 - f.x, v1 - f.y);
            const size_t e = (size_t)(b * SEQ + row) * D_MODEL + d0;
            *(uint32_t*)(g_Ah + e) = uh;
            *(uint32_t*)(g_Al + e) = ul;
        }
    }
}

// ---------------- launch ----------------
extern "C" void kernel_launch(void* const* d_in, const int* in_sizes, int n_in,
                              void* d_out, int out_size)
{
    const float* x  = (const float*)d_in[0];
    const float* Wq = (const float*)d_in[1];
    const float* bq = (const float*)d_in[2];
    const float* Wk = (const float*)d_in[3];
    const float* bk = (const float*)d_in[4];
    const float* Wv = (const float*)d_in[5];
    const float* bv = (const float*)d_in[6];
    const float* Wo = (const float*)d_in[7];
    float* out = (float*)d_out;

    const int qkvSmem = 2 * QSTAGE;                                   // 184320
    cudaFuncSetAttribute(gemm_qkv, cudaFuncAttributeMaxDynamicSharedMemorySize, qkvSmem);
    const int woSmem = 2 * WSTAGE;                                    // 61440
    cudaFuncSetAttribute(gemm_wo, cudaFuncAttributeMaxDynamicSharedMemorySize, woSmem);
    const int flashSmem = (2 * QTILE + 2 * KVSTG) * (int)sizeof(__half);  // 110592
    cudaFuncSetAttribute(flash_mma, cudaFuncAttributeMaxDynamicSharedMemorySize, flashSmem);

    cvt_rm<<<M_ROWS * D_MODEL / 4 / 256, 256>>>(x);
    cvt_wt<<<dim3(D_MODEL / 32, D_MODEL / 32, 4), 256>>>(Wq, Wk, Wv, Wo);
    gemm_qkv<<<dim3(D_MODEL / 128, M_ROWS / 128), 512, qkvSmem>>>(bq, bk, bv);
    flash_mma<<<dim3(SEQ / 128, N_HEADS, BATCH), 256, flashSmem>>>();
    gemm_wo<<<dim3(D_MODEL / 128, M_ROWS / 128), 256, woSmem>>>(out);
}